// round 14
// baseline (speedup 1.0000x reference)
#include <cuda_runtime.h>
#include <cuda_fp16.h>
#include <cstdint>

#define D_MODEL 1024
#define BATCH 2
#define SEQ 2048
#define NHEAD 16
#define HD 64
#define MROWS (BATCH * SEQ)   // 4096

// -------- scratch (no cudaMalloc allowed) --------
__device__ __half g_qh[MROWS * D_MODEL];
__device__ __half g_kh[MROWS * D_MODEL];
__device__ __half g_vt[BATCH * NHEAD * HD * SEQ];   // [b][h][d][s]
__device__ __half g_ah[MROWS * D_MODEL];
__device__ __half g_xh[MROWS * D_MODEL];
__device__ __half g_wt[4 * D_MODEL * D_MODEL];      // [Wq|Wk|Wv|Wo] transposed: row n, col k

// ============================================================
// helpers
// ============================================================
__device__ __forceinline__ void mma_f16(float c[4], const uint32_t a[4],
                                        uint32_t b0, uint32_t b1) {
    asm volatile(
        "mma.sync.aligned.m16n8k16.row.col.f32.f16.f16.f32 "
        "{%0,%1,%2,%3}, {%4,%5,%6,%7}, {%8,%9}, {%0,%1,%2,%3};"
        : "+f"(c[0]), "+f"(c[1]), "+f"(c[2]), "+f"(c[3])
        : "r"(a[0]), "r"(a[1]), "r"(a[2]), "r"(a[3]), "r"(b0), "r"(b1));
}
__device__ __forceinline__ uint32_t pack2(float lo, float hi) {
    __half2 h = __floats2half2_rn(lo, hi);
    return *(uint32_t*)&h;
}
__device__ __forceinline__ uint32_t smem_u32(const void* p) {
    uint32_t a;
    asm("{ .reg .u64 t; cvta.to.shared.u64 t, %1; cvt.u32.u64 %0, t; }" : "=r"(a) : "l"(p));
    return a;
}
__device__ __forceinline__ void cpasync16(uint32_t dst, const void* src) {
    asm volatile("cp.async.cg.shared.global [%0], [%1], 16;" :: "r"(dst), "l"(src));
}
#define CP_COMMIT() asm volatile("cp.async.commit_group;" ::: "memory")
#define CP_WAIT(n)  asm volatile("cp.async.wait_group %0;" :: "n"(n) : "memory")
#define LDSM4(r0, r1, r2, r3, addr) \
    asm volatile("ldmatrix.sync.aligned.m8n8.x4.shared.b16 {%0,%1,%2,%3}, [%4];" \
        : "=r"(r0), "=r"(r1), "=r"(r2), "=r"(r3) : "r"(addr))

// ============================================================
// pre-pass: x -> fp16 ; weights -> fp16 transposed [n][k]
// ============================================================
__global__ __launch_bounds__(256) void x2h_kernel(
    const float* __restrict__ in, __half* __restrict__ out, int n4)
{
    int i = blockIdx.x * 256 + threadIdx.x;
    if (i < n4) {
        float4 v = ((const float4*)in)[i];
        __half2 h0 = __floats2half2_rn(v.x, v.y);
        __half2 h1 = __floats2half2_rn(v.z, v.w);
        uint2 u;
        u.x = *(uint32_t*)&h0;
        u.y = *(uint32_t*)&h1;
        ((uint2*)out)[i] = u;
    }
}

__global__ __launch_bounds__(256) void wtrans_kernel(
    const float* __restrict__ w0, const float* __restrict__ w1,
    const float* __restrict__ w2, const float* __restrict__ w3,
    __half* __restrict__ wt)
{
    __shared__ float t[32][33];
    const int seg = blockIdx.z;
    const float* W = (seg == 0) ? w0 : (seg == 1) ? w1 : (seg == 2) ? w2 : w3;
    const int n0 = blockIdx.x * 32;
    const int k0 = blockIdx.y * 32;
    const int tx = threadIdx.x & 31;
    const int ty = threadIdx.x >> 5;   // 0..7
#pragma unroll
    for (int i = 0; i < 4; i++)
        t[ty + 8 * i][tx] = W[(long)(k0 + ty + 8 * i) * 1024 + n0 + tx];
    __syncthreads();
#pragma unroll
    for (int i = 0; i < 4; i++) {
        int n = n0 + ty + 8 * i;
        wt[(long)(seg * 1024 + n) * 1024 + k0 + tx] = __float2half_rn(t[tx][ty + 8 * i]);
    }
}

// ============================================================
// fp16 GEMM (templated warp-N width NI: CTA tile 128 x 32*NI).
// mma m16n8k16 + ldmatrix, 4-stage cp.async pipeline, BK=32, 256 thr.
// Warp grid 2(M) x 4(N); warp tile 64 x 8*NI.
// ============================================================
#define AST_W 20                 // smem row stride in words (16 data + 4 pad)
#define ABUF_W (128 * AST_W)     // A stage buffer words

template<int NI>
__global__ __launch_bounds__(256, (NI == 4) ? 2 : 1) void gemm_h_kernel(
    const __half* __restrict__ A, const __half* __restrict__ W,
    const float* __restrict__ bias0, const float* __restrict__ bias2,
    __half* __restrict__ Cq, __half* __restrict__ Ck, __half* __restrict__ Cvt,
    float* __restrict__ Cf, float qscale, float kscale, int out_mode)
{
    constexpr int BN = 32 * NI;            // CTA N width
    constexpr int BBUF_W = BN * AST_W;     // B stage buffer words
    extern __shared__ uint32_t smw[];
    const uint32_t sbase = smem_u32(smw);
    const uint32_t bstage0 = 4 * ABUF_W;

    const int tid = threadIdx.x;
    const int warp = tid >> 5;
    const int lane = tid & 31;
    const int wm = warp & 1;
    const int wn = warp >> 1;
    const int m0 = blockIdx.y * 128;
    const int n0g = blockIdx.x * BN;
    const int g = lane >> 2;
    const int t4 = lane & 3;

    const uint32_t aa_off = (uint32_t)((wm * 64 + (lane & 15)) * AST_W + ((lane & 16) ? 4 : 0));
    const uint32_t bb_off = (uint32_t)((wn * 8 * NI + (lane & 7) + ((lane & 16) ? 8 : 0)) * AST_W
                                       + ((lane & 8) ? 4 : 0));

    float acc[4][NI][4];
#pragma unroll
    for (int i = 0; i < 4; i++)
#pragma unroll
        for (int j = 0; j < NI; j++)
#pragma unroll
            for (int c = 0; c < 4; c++) acc[i][j][c] = 0.f;

    auto issue_tile = [&](int buf, int k0) {
#pragma unroll
        for (int i = 0; i < 2; i++) {
            int c = i * 256 + tid;
            int row = c >> 2, cw = c & 3;
            cpasync16(sbase + (uint32_t)(buf * ABUF_W + row * AST_W + cw * 4) * 4,
                      (const char*)A + ((long)(m0 + row) * 1024 + k0) * 2 + cw * 16);
        }
#pragma unroll
        for (int i = 0; i < NI / 2; i++) {
            int c = i * 256 + tid;
            int row = c >> 2, cw = c & 3;
            cpasync16(sbase + (uint32_t)(bstage0 + buf * BBUF_W + row * AST_W + cw * 4) * 4,
                      (const char*)W + ((long)(n0g + row) * 1024 + k0) * 2 + cw * 16);
        }
        CP_COMMIT();
    };

    issue_tile(0, 0);
    issue_tile(1, 32);
    issue_tile(2, 64);

    for (int kt = 0; kt < 32; ++kt) {
        if (kt < 30)      { CP_WAIT(2); }
        else if (kt == 30){ CP_WAIT(1); }
        else              { CP_WAIT(0); }
        __syncthreads();
        if (kt + 3 < 32) issue_tile((kt + 3) & 3, (kt + 3) * 32);

        const uint32_t abase = sbase + ((kt & 3) * ABUF_W + aa_off) * 4;
        const uint32_t bbase = sbase + (bstage0 + (kt & 3) * BBUF_W + bb_off) * 4;
#pragma unroll
        for (int ks = 0; ks < 2; ks++) {
            uint32_t af[4][4], bf[NI][2];
#pragma unroll
            for (int mi = 0; mi < 4; mi++)
                LDSM4(af[mi][0], af[mi][1], af[mi][2], af[mi][3],
                      abase + (uint32_t)(mi * 16 * AST_W + ks * 8) * 4);
#pragma unroll
            for (int nb = 0; nb < NI / 2; nb++)
                LDSM4(bf[2 * nb][0], bf[2 * nb][1], bf[2 * nb + 1][0], bf[2 * nb + 1][1],
                      bbase + (uint32_t)(nb * 16 * AST_W + ks * 8) * 4);
#pragma unroll
            for (int mi = 0; mi < 4; mi++)
#pragma unroll
                for (int ni = 0; ni < NI; ni++)
                    mma_f16(acc[mi][ni], af[mi], bf[ni][0], bf[ni][1]);
        }
    }

    // ---- epilogue ----
    if (out_mode == 1) {
#pragma unroll
        for (int mi = 0; mi < 4; mi++) {
            int row = m0 + wm * 64 + mi * 16 + g;
#pragma unroll
            for (int ni = 0; ni < NI; ni++) {
                int col = n0g + wn * 8 * NI + ni * 8 + 2 * t4;
                float b0 = bias0[col], b1 = bias0[col + 1];
                float2 r0 = {acc[mi][ni][0] + b0, acc[mi][ni][1] + b1};
                float2 r1 = {acc[mi][ni][2] + b0, acc[mi][ni][3] + b1};
                *(float2*)&Cf[(long)row * 1024 + col] = r0;
                *(float2*)&Cf[(long)(row + 8) * 1024 + col] = r1;
            }
        }
    } else {
#pragma unroll
        for (int mi = 0; mi < 4; mi++) {
            int row = m0 + wm * 64 + mi * 16 + g;
#pragma unroll
            for (int ni = 0; ni < NI; ni++) {
                int colg = n0g + wn * 8 * NI + ni * 8 + 2 * t4;
                int seg = colg >> 10;
                int col = colg & 1023;
                if (seg == 0) {
                    float b0 = bias0[col], b1 = bias0[col + 1];
                    __half2 h0 = __floats2half2_rn((acc[mi][ni][0] + b0) * qscale,
                                                   (acc[mi][ni][1] + b1) * qscale);
                    __half2 h1 = __floats2half2_rn((acc[mi][ni][2] + b0) * qscale,
                                                   (acc[mi][ni][3] + b1) * qscale);
                    *(__half2*)&Cq[(long)row * 1024 + col] = h0;
                    *(__half2*)&Cq[(long)(row + 8) * 1024 + col] = h1;
                } else if (seg == 1) {
                    __half2 h0 = __floats2half2_rn(acc[mi][ni][0] * kscale,
                                                   acc[mi][ni][1] * kscale);
                    __half2 h1 = __floats2half2_rn(acc[mi][ni][2] * kscale,
                                                   acc[mi][ni][3] * kscale);
                    *(__half2*)&Ck[(long)row * 1024 + col] = h0;
                    *(__half2*)&Ck[(long)(row + 8) * 1024 + col] = h1;
                } else {
                    float b0 = bias2[col], b1 = bias2[col + 1];
                    int b_ = row >> 11, s_ = row & 2047;
                    int h_ = col >> 6, d_ = col & 63;
                    long base = ((long)(b_ * NHEAD + h_) * HD + d_) * SEQ;
                    Cvt[base + s_]            = __float2half_rn(acc[mi][ni][0] + b0);
                    Cvt[base + SEQ + s_]      = __float2half_rn(acc[mi][ni][1] + b1);
                    Cvt[base + s_ + 8]        = __float2half_rn(acc[mi][ni][2] + b0);
                    Cvt[base + SEQ + s_ + 8]  = __float2half_rn(acc[mi][ni][3] + b1);
                }
            }
        }
    }
}

#define GEMM_SMEM_QKV ((4 * ABUF_W + 4 * 256 * AST_W) * 4)   // NI=8: 122880
#define GEMM_SMEM_OUT ((4 * ABUF_W + 4 * 128 * AST_W) * 4)   // NI=4: 81920

// ============================================================
// fp16 flash attention (causal), mma m16n8k16 + ldmatrix.
// q pre-scaled by log2(e) -> softmax via exp2f (no per-element mul).
// Paired q-tiles (p, 15-p), BM=128, BN=64, 256 threads.
// ============================================================
#define QST_W 36
#define Q_W   (128 * QST_W)
#define KV_W  (64 * QST_W)
#define ATTN_SMEM_BYTES ((Q_W + 4 * KV_W) * 4)   // 55296

__global__ __launch_bounds__(256, 2) void attn_h_kernel(
    const __half* __restrict__ q, const __half* __restrict__ k,
    const __half* __restrict__ vt, __half* __restrict__ out)
{
    extern __shared__ uint32_t smw[];
    const uint32_t sbase = smem_u32(smw);
    const int kwoff = Q_W;
    const int vwoff = Q_W + 2 * KV_W;

    const int tid = threadIdx.x;
    const int warp = tid >> 5;
    const int lane = tid & 31;
    const int g = lane >> 2;
    const int t4 = lane & 3;
    const int rw = warp * 16;

    const int pair = blockIdx.x;
    const int h  = blockIdx.y;
    const int b  = blockIdx.z;
    const int NQT = SEQ / 128;

    const uint32_t qa_off = (uint32_t)((rw + (lane & 15)) * QST_W + ((lane & 16) ? 4 : 0));
    const uint32_t kb_off = (uint32_t)(((lane & 7) + ((lane & 16) ? 8 : 0)) * QST_W
                                       + ((lane & 8) ? 4 : 0));

    const __half* qbase = q + (long)b * SEQ * D_MODEL + h * HD;
    const __half* kbase = k + (long)b * SEQ * D_MODEL + h * HD;
    const __half* vbase = vt + ((long)(b * NHEAD + h) * HD) * SEQ;

    auto issue_kv = [&](int buf, int kr0) {
#pragma unroll
        for (int i = 0; i < 2; i++) {
            int c = i * 256 + tid;
            int row = c >> 3, cw = c & 7;
            cpasync16(sbase + (uint32_t)(kwoff + buf * KV_W + row * QST_W + cw * 4) * 4,
                      (const char*)kbase + ((long)(kr0 + row) * 1024) * 2 + cw * 16);
            cpasync16(sbase + (uint32_t)(vwoff + buf * KV_W + row * QST_W + cw * 4) * 4,
                      (const char*)vbase + ((long)row * SEQ + kr0) * 2 + cw * 16);
        }
        CP_COMMIT();
    };

#pragma unroll 1
    for (int pass = 0; pass < 2; pass++) {
        const int qb = pass ? pair : (NQT - 1 - pair);
        const int r0 = qb * 128;
        const int wrow = r0 + rw;

        if (pass) __syncthreads();

#pragma unroll
        for (int i = 0; i < 2; i++) {
            int c = i * 256 + tid;
            int row = c >> 3, cw = c & 7;
            cpasync16(sbase + (uint32_t)(kwoff + row * QST_W + cw * 4) * 4,
                      (const char*)kbase + ((long)row * 1024) * 2 + cw * 16);
            cpasync16(sbase + (uint32_t)(vwoff + row * QST_W + cw * 4) * 4,
                      (const char*)vbase + ((long)row * SEQ) * 2 + cw * 16);
        }
#pragma unroll
        for (int i = 0; i < 4; i++) {
            int c = i * 256 + tid;
            int row = c >> 3, cw = c & 7;
            cpasync16(sbase + (uint32_t)(row * QST_W + cw * 4) * 4,
                      (const char*)qbase + ((long)(r0 + row) * 1024) * 2 + cw * 16);
        }
        CP_COMMIT();

        float m0r = -3.0e38f, m1r = -3.0e38f, l0r = 0.f, l1r = 0.f;
        float o[8][4];
#pragma unroll
        for (int ni = 0; ni < 8; ni++)
#pragma unroll
            for (int c = 0; c < 4; c++) o[ni][c] = 0.f;

        const int kb_max = 2 * qb + 1;
        for (int kb = 0; kb <= kb_max; kb++) {
            const int buf = kb & 1;
            CP_WAIT(0);
            __syncthreads();
            if (kb + 1 <= kb_max) issue_kv(buf ^ 1, (kb + 1) * 64);

            const int kr0 = kb * 64;
            const uint32_t kbb = sbase + (uint32_t)(kwoff + buf * KV_W + kb_off) * 4;
            const uint32_t vbb = sbase + (uint32_t)(vwoff + buf * KV_W + kb_off) * 4;

            if (kr0 <= wrow + 15) {
                const bool need_mask = (kr0 + 63 > wrow);

                float s[8][4];
#pragma unroll
                for (int ni = 0; ni < 8; ni++)
#pragma unroll
                    for (int c = 0; c < 4; c++) s[ni][c] = 0.f;

                // ---- S = Q K^T  (S already in log2 domain via q scaling) ----
#pragma unroll
                for (int ks = 0; ks < 4; ks++) {
                    uint32_t a[4];
                    LDSM4(a[0], a[1], a[2], a[3],
                          sbase + (qa_off + (uint32_t)(ks * 8)) * 4);
                    uint32_t bf[8][2];
#pragma unroll
                    for (int nb = 0; nb < 4; nb++)
                        LDSM4(bf[2 * nb][0], bf[2 * nb][1],
                              bf[2 * nb + 1][0], bf[2 * nb + 1][1],
                              kbb + (uint32_t)(nb * 16 * QST_W + ks * 8) * 4);
#pragma unroll
                    for (int ni = 0; ni < 8; ni++)
                        mma_f16(s[ni], a, bf[ni][0], bf[ni][1]);
                }

                // ---- causal mask ----
                if (need_mask) {
                    int rg0 = wrow + g, rg1 = wrow + g + 8;
#pragma unroll
                    for (int ni = 0; ni < 8; ni++) {
                        int col = kr0 + ni * 8 + 2 * t4;
                        if (col     > rg0) s[ni][0] = -1e9f;
                        if (col + 1 > rg0) s[ni][1] = -1e9f;
                        if (col     > rg1) s[ni][2] = -1e9f;
                        if (col + 1 > rg1) s[ni][3] = -1e9f;
                    }
                }

                // ---- online softmax (base-2) ----
                float mx0 = -3.0e38f, mx1 = -3.0e38f;
#pragma unroll
                for (int ni = 0; ni < 8; ni++) {
                    mx0 = fmaxf(mx0, fmaxf(s[ni][0], s[ni][1]));
                    mx1 = fmaxf(mx1, fmaxf(s[ni][2], s[ni][3]));
                }
                mx0 = fmaxf(mx0, __shfl_xor_sync(0xffffffffu, mx0, 1));
                mx0 = fmaxf(mx0, __shfl_xor_sync(0xffffffffu, mx0, 2));
                mx1 = fmaxf(mx1, __shfl_xor_sync(0xffffffffu, mx1, 1));
                mx1 = fmaxf(mx1, __shfl_xor_sync(0xffffffffu, mx1, 2));

                float mn0 = fmaxf(m0r, mx0), mn1 = fmaxf(m1r, mx1);
                float al0 = exp2f(m0r - mn0), al1 = exp2f(m1r - mn1);
                m0r = mn0; m1r = mn1;

                float rs0 = 0.f, rs1 = 0.f;
#pragma unroll
                for (int ni = 0; ni < 8; ni++) {
                    s[ni][0] = exp2f(s[ni][0] - mn0);
                    s[ni][1] = exp2f(s[ni][1] - mn0);
                    s[ni][2] = exp2f(s[ni][2] - mn1);
                    s[ni][3] = exp2f(s[ni][3] - mn1);
                    rs0 += s[ni][0] + s[ni][1];
                    rs1 += s[ni][2] + s[ni][3];
                }
                rs0 += __shfl_xor_sync(0xffffffffu, rs0, 1);
                rs0 += __shfl_xor_sync(0xffffffffu, rs0, 2);
                rs1 += __shfl_xor_sync(0xffffffffu, rs1, 1);
                rs1 += __shfl_xor_sync(0xffffffffu, rs1, 2);
                l0r = l0r * al0 + rs0;
                l1r = l1r * al1 + rs1;

#pragma unroll
                for (int ni = 0; ni < 8; ni++) {
                    o[ni][0] *= al0; o[ni][1] *= al0;
                    o[ni][2] *= al1; o[ni][3] *= al1;
                }

                // ---- O += P V : P by register packing, V by ldmatrix ----
#pragma unroll
                for (int j = 0; j < 4; j++) {
                    uint32_t a[4];
                    a[0] = pack2(s[2 * j][0],     s[2 * j][1]);
                    a[1] = pack2(s[2 * j][2],     s[2 * j][3]);
                    a[2] = pack2(s[2 * j + 1][0], s[2 * j + 1][1]);
                    a[3] = pack2(s[2 * j + 1][2], s[2 * j + 1][3]);
                    uint32_t bf[8][2];
#pragma unroll
                    for (int nb = 0; nb < 4; nb++)
                        LDSM4(bf[2 * nb][0], bf[2 * nb][1],
                              bf[2 * nb + 1][0], bf[2 * nb + 1][1],
                              vbb + (uint32_t)(nb * 16 * QST_W + j * 8) * 4);
#pragma unroll
                    for (int ni = 0; ni < 8; ni++)
                        mma_f16(o[ni], a, bf[ni][0], bf[ni][1]);
                }
            }
        }

        // ---- normalize + write half [B,S,H,hd] ----
        float inv0 = 1.0f / l0r, inv1 = 1.0f / l1r;
        int row0 = r0 + rw + g, row1 = row0 + 8;
#pragma unroll
        for (int ni = 0; ni < 8; ni++) {
            int col = h * HD + ni * 8 + 2 * t4;
            __half2 w0 = __floats2half2_rn(o[ni][0] * inv0, o[ni][1] * inv0);
            __half2 w1 = __floats2half2_rn(o[ni][2] * inv1, o[ni][3] * inv1);
            *(__half2*)&out[((long)b * SEQ + row0) * D_MODEL + col] = w0;
            *(__half2*)&out[((long)b * SEQ + row1) * D_MODEL + col] = w1;
        }
    }
}

// ============================================================
// launch
// ============================================================
extern "C" void kernel_launch(void* const* d_in, const int* in_sizes, int n_in,
                              void* d_out, int out_size)
{
    (void)in_sizes; (void)n_in; (void)out_size;
    const float* x  = (const float*)d_in[0];
    const float* Wq = (const float*)d_in[2];
    const float* bq = (const float*)d_in[3];
    const float* Wk = (const float*)d_in[4];
    const float* Wv = (const float*)d_in[5];
    const float* bv = (const float*)d_in[6];
    const float* Wo = (const float*)d_in[7];
    const float* bo = (const float*)d_in[8];
    float* out = (float*)d_out;

    __half *qh, *kh, *vt, *ah, *xh, *wt;
    cudaGetSymbolAddress((void**)&qh, g_qh);
    cudaGetSymbolAddress((void**)&kh, g_kh);
    cudaGetSymbolAddress((void**)&vt, g_vt);
    cudaGetSymbolAddress((void**)&ah, g_ah);
    cudaGetSymbolAddress((void**)&xh, g_xh);
    cudaGetSymbolAddress((void**)&wt, g_wt);
    __half* wot = wt + (long)3 * D_MODEL * D_MODEL;

    const float scale = 0.3535533905932738f;          // 64^-0.25
    const float log2e = 1.4426950408889634f;
    const float qscale = scale * log2e;               // folds exp->exp2

    static bool attr_set = false;
    if (!attr_set) {
        cudaFuncSetAttribute(attn_h_kernel, cudaFuncAttributeMaxDynamicSharedMemorySize,
                             ATTN_SMEM_BYTES);
        cudaFuncSetAttribute(gemm_h_kernel<8>, cudaFuncAttributeMaxDynamicSharedMemorySize,
                             GEMM_SMEM_QKV);
        cudaFuncSetAttribute(gemm_h_kernel<4>, cudaFuncAttributeMaxDynamicSharedMemorySize,
                             GEMM_SMEM_OUT);
        attr_set = true;
    }

    // pre-pass: fp16 conversions
    const int x4 = MROWS * D_MODEL / 4;
    x2h_kernel<<<(x4 + 255) / 256, 256>>>(x, xh, x4);
    dim3 wg(32, 32, 4);
    wtrans_kernel<<<wg, 256>>>(Wq, Wk, Wv, Wo, wt);

    // fused QKV projection: CTA tile 128x256
    dim3 gqkv(12, 32);
    gemm_h_kernel<8><<<gqkv, 256, GEMM_SMEM_QKV>>>(
        xh, wt, bq, bv, qh, kh, vt, nullptr, qscale, scale, 0);

    // balanced paired attention
    dim3 ag(SEQ / 256, NHEAD, BATCH);
    attn_h_kernel<<<ag, 256, ATTN_SMEM_BYTES>>>(qh, kh, vt, ah);

    // output projection (fp32 out + bo), CTA tile 128x128
    dim3 go(8, 32);
    gemm_h_kernel<4><<<go, 256, GEMM_SMEM_OUT>>>(
        ah, wot, bo, nullptr, nullptr, nullptr, nullptr, out, 1.0f, 1.0f, 1);
}

// round 16
// speedup vs baseline: 1.0861x; 1.0861x over previous
#include <cuda_runtime.h>
#include <cuda_fp16.h>
#include <cstdint>

#define D_MODEL 1024
#define BATCH 2
#define SEQ 2048
#define NHEAD 16
#define HD 64
#define MROWS (BATCH * SEQ)   // 4096

// -------- scratch (no cudaMalloc allowed) --------
__device__ __half g_qh[MROWS * D_MODEL];
__device__ __half g_kh[MROWS * D_MODEL];
__device__ __half g_vt[BATCH * NHEAD * HD * SEQ];   // [b][h][d][s]
__device__ __half g_ah[MROWS * D_MODEL];
__device__ __half g_xh[MROWS * D_MODEL];
__device__ __half g_wt[4 * D_MODEL * D_MODEL];      // [Wq|Wk|Wv|Wo] transposed: row n, col k

// ============================================================
// helpers
// ============================================================
__device__ __forceinline__ void mma_f16(float c[4], const uint32_t a[4],
                                        uint32_t b0, uint32_t b1) {
    asm volatile(
        "mma.sync.aligned.m16n8k16.row.col.f32.f16.f16.f32 "
        "{%0,%1,%2,%3}, {%4,%5,%6,%7}, {%8,%9}, {%0,%1,%2,%3};"
        : "+f"(c[0]), "+f"(c[1]), "+f"(c[2]), "+f"(c[3])
        : "r"(a[0]), "r"(a[1]), "r"(a[2]), "r"(a[3]), "r"(b0), "r"(b1));
}
__device__ __forceinline__ uint32_t pack2(float lo, float hi) {
    __half2 h = __floats2half2_rn(lo, hi);
    return *(uint32_t*)&h;
}
__device__ __forceinline__ uint32_t smem_u32(const void* p) {
    uint32_t a;
    asm("{ .reg .u64 t; cvta.to.shared.u64 t, %1; cvt.u32.u64 %0, t; }" : "=r"(a) : "l"(p));
    return a;
}
__device__ __forceinline__ void cpasync16(uint32_t dst, const void* src) {
    asm volatile("cp.async.cg.shared.global [%0], [%1], 16;" :: "r"(dst), "l"(src));
}
#define CP_COMMIT() asm volatile("cp.async.commit_group;" ::: "memory")
#define CP_WAIT(n)  asm volatile("cp.async.wait_group %0;" :: "n"(n) : "memory")
#define LDSM4(r0, r1, r2, r3, addr) \
    asm volatile("ldmatrix.sync.aligned.m8n8.x4.shared.b16 {%0,%1,%2,%3}, [%4];" \
        : "=r"(r0), "=r"(r1), "=r"(r2), "=r"(r3) : "r"(addr))

// ============================================================
// pre-pass: x -> fp16 ; weights -> fp16 transposed [n][k]
// ============================================================
__global__ __launch_bounds__(256) void x2h_kernel(
    const float* __restrict__ in, __half* __restrict__ out, int n4)
{
    int i = blockIdx.x * 256 + threadIdx.x;
    if (i < n4) {
        float4 v = ((const float4*)in)[i];
        __half2 h0 = __floats2half2_rn(v.x, v.y);
        __half2 h1 = __floats2half2_rn(v.z, v.w);
        uint2 u;
        u.x = *(uint32_t*)&h0;
        u.y = *(uint32_t*)&h1;
        ((uint2*)out)[i] = u;
    }
}

__global__ __launch_bounds__(256) void wtrans_kernel(
    const float* __restrict__ w0, const float* __restrict__ w1,
    const float* __restrict__ w2, const float* __restrict__ w3,
    __half* __restrict__ wt)
{
    __shared__ float t[32][33];
    const int seg = blockIdx.z;
    const float* W = (seg == 0) ? w0 : (seg == 1) ? w1 : (seg == 2) ? w2 : w3;
    const int n0 = blockIdx.x * 32;
    const int k0 = blockIdx.y * 32;
    const int tx = threadIdx.x & 31;
    const int ty = threadIdx.x >> 5;   // 0..7
#pragma unroll
    for (int i = 0; i < 4; i++)
        t[ty + 8 * i][tx] = W[(long)(k0 + ty + 8 * i) * 1024 + n0 + tx];
    __syncthreads();
#pragma unroll
    for (int i = 0; i < 4; i++) {
        int n = n0 + ty + 8 * i;
        wt[(long)(seg * 1024 + n) * 1024 + k0 + tx] = __float2half_rn(t[tx][ty + 8 * i]);
    }
}

// ============================================================
// fp16 GEMM via mma.sync m16n8k16 + ldmatrix, 4-stage cp.async pipeline.
// A [m][k] half; Wt [n][k] half. CTA 128x128, BK=32, 256 threads.
// Warp grid 2(M)x4(N), warp tile 64x32. (Proven R12 config: 2 CTAs/SM.)
// ============================================================
#define AST_W 20                 // smem row stride in words (16 data + 4 pad)
#define ABUF_W (128 * AST_W)     // 2560 words per stage buffer
#define GEMM_SMEM_BYTES (8 * ABUF_W * 4)   // 81920

__global__ __launch_bounds__(256, 2) void gemm_h_kernel(
    const __half* __restrict__ A, const __half* __restrict__ W,
    const float* __restrict__ bias0, const float* __restrict__ bias2,
    __half* __restrict__ Cq, __half* __restrict__ Ck, __half* __restrict__ Cvt,
    float* __restrict__ Cf, float qscale, float kscale, int out_mode)
{
    extern __shared__ uint32_t smw[];
    const uint32_t sbase = smem_u32(smw);

    const int tid = threadIdx.x;
    const int warp = tid >> 5;
    const int lane = tid & 31;
    const int wm = warp & 1;
    const int wn = warp >> 1;
    const int m0 = blockIdx.y * 128;
    const int n0g = blockIdx.x * 128;
    const int g = lane >> 2;
    const int t4 = lane & 3;

    // ldmatrix lane-offset bases (in words)
    const uint32_t aa_off = (uint32_t)((wm * 64 + (lane & 15)) * AST_W + ((lane & 16) ? 4 : 0));
    const uint32_t bb_off = (uint32_t)((wn * 32 + (lane & 7) + ((lane & 16) ? 8 : 0)) * AST_W
                                       + ((lane & 8) ? 4 : 0));

    float acc[4][4][4];
#pragma unroll
    for (int i = 0; i < 4; i++)
#pragma unroll
        for (int j = 0; j < 4; j++)
#pragma unroll
            for (int c = 0; c < 4; c++) acc[i][j][c] = 0.f;

    auto issue_tile = [&](int buf, int k0) {
#pragma unroll
        for (int i = 0; i < 2; i++) {
            int c = i * 256 + tid;
            int row = c >> 2, cw = c & 3;
            cpasync16(sbase + (uint32_t)(buf * ABUF_W + row * AST_W + cw * 4) * 4,
                      (const char*)A + ((long)(m0 + row) * 1024 + k0) * 2 + cw * 16);
        }
#pragma unroll
        for (int i = 0; i < 2; i++) {
            int c = i * 256 + tid;
            int row = c >> 2, cw = c & 3;
            cpasync16(sbase + (uint32_t)((4 + buf) * ABUF_W + row * AST_W + cw * 4) * 4,
                      (const char*)W + ((long)(n0g + row) * 1024 + k0) * 2 + cw * 16);
        }
        CP_COMMIT();
    };

    issue_tile(0, 0);
    issue_tile(1, 32);
    issue_tile(2, 64);

    for (int kt = 0; kt < 32; ++kt) {
        if (kt < 30)      { CP_WAIT(2); }
        else if (kt == 30){ CP_WAIT(1); }
        else              { CP_WAIT(0); }
        __syncthreads();
        if (kt + 3 < 32) issue_tile((kt + 3) & 3, (kt + 3) * 32);

        const uint32_t abase = sbase + ((kt & 3) * ABUF_W + aa_off) * 4;
        const uint32_t bbase = sbase + ((4 + (kt & 3)) * ABUF_W + bb_off) * 4;
#pragma unroll
        for (int ks = 0; ks < 2; ks++) {
            uint32_t af[4][4], bf[4][2];
#pragma unroll
            for (int mi = 0; mi < 4; mi++)
                LDSM4(af[mi][0], af[mi][1], af[mi][2], af[mi][3],
                      abase + (uint32_t)(mi * 16 * AST_W + ks * 8) * 4);
#pragma unroll
            for (int nb = 0; nb < 2; nb++)
                LDSM4(bf[2 * nb][0], bf[2 * nb][1], bf[2 * nb + 1][0], bf[2 * nb + 1][1],
                      bbase + (uint32_t)(nb * 16 * AST_W + ks * 8) * 4);
#pragma unroll
            for (int mi = 0; mi < 4; mi++)
#pragma unroll
                for (int ni = 0; ni < 4; ni++)
                    mma_f16(acc[mi][ni], af[mi], bf[ni][0], bf[ni][1]);
        }
    }

    // ---- epilogue ----
    if (out_mode == 1) {
#pragma unroll
        for (int mi = 0; mi < 4; mi++) {
            int row = m0 + wm * 64 + mi * 16 + g;
#pragma unroll
            for (int ni = 0; ni < 4; ni++) {
                int col = n0g + wn * 32 + ni * 8 + 2 * t4;
                float b0 = bias0[col], b1 = bias0[col + 1];
                float2 r0 = {acc[mi][ni][0] + b0, acc[mi][ni][1] + b1};
                float2 r1 = {acc[mi][ni][2] + b0, acc[mi][ni][3] + b1};
                *(float2*)&Cf[(long)row * 1024 + col] = r0;
                *(float2*)&Cf[(long)(row + 8) * 1024 + col] = r1;
            }
        }
    } else {
        const int seg = n0g >> 10;
        const int n0 = n0g & 1023;
#pragma unroll
        for (int mi = 0; mi < 4; mi++) {
            int row = m0 + wm * 64 + mi * 16 + g;
#pragma unroll
            for (int ni = 0; ni < 4; ni++) {
                int col = n0 + wn * 32 + ni * 8 + 2 * t4;
                if (seg == 0) {
                    float b0 = bias0[col], b1 = bias0[col + 1];
                    __half2 h0 = __floats2half2_rn((acc[mi][ni][0] + b0) * qscale,
                                                   (acc[mi][ni][1] + b1) * qscale);
                    __half2 h1 = __floats2half2_rn((acc[mi][ni][2] + b0) * qscale,
                                                   (acc[mi][ni][3] + b1) * qscale);
                    *(__half2*)&Cq[(long)row * 1024 + col] = h0;
                    *(__half2*)&Cq[(long)(row + 8) * 1024 + col] = h1;
                } else if (seg == 1) {
                    __half2 h0 = __floats2half2_rn(acc[mi][ni][0] * kscale,
                                                   acc[mi][ni][1] * kscale);
                    __half2 h1 = __floats2half2_rn(acc[mi][ni][2] * kscale,
                                                   acc[mi][ni][3] * kscale);
                    *(__half2*)&Ck[(long)row * 1024 + col] = h0;
                    *(__half2*)&Ck[(long)(row + 8) * 1024 + col] = h1;
                } else {
                    float b0 = bias2[col], b1 = bias2[col + 1];
                    int b_ = row >> 11, s_ = row & 2047;
                    int h_ = col >> 6, d_ = col & 63;
                    long base = ((long)(b_ * NHEAD + h_) * HD + d_) * SEQ;
                    Cvt[base + s_]            = __float2half_rn(acc[mi][ni][0] + b0);
                    Cvt[base + SEQ + s_]      = __float2half_rn(acc[mi][ni][1] + b1);
                    Cvt[base + s_ + 8]        = __float2half_rn(acc[mi][ni][2] + b0);
                    Cvt[base + SEQ + s_ + 8]  = __float2half_rn(acc[mi][ni][3] + b1);
                }
            }
        }
    }
}

// ============================================================
// fp16 flash attention (causal), mma m16n8k16 + ldmatrix.
// q pre-scaled by log2(e) -> softmax via exp2f.
// Paired q-tiles (p, 15-p), BM=128, BN=64, 256 threads.
// ============================================================
#define QST_W 36
#define Q_W   (128 * QST_W)
#define KV_W  (64 * QST_W)
#define ATTN_SMEM_BYTES ((Q_W + 4 * KV_W) * 4)   // 55296

__global__ __launch_bounds__(256, 2) void attn_h_kernel(
    const __half* __restrict__ q, const __half* __restrict__ k,
    const __half* __restrict__ vt, __half* __restrict__ out)
{
    extern __shared__ uint32_t smw[];
    const uint32_t sbase = smem_u32(smw);
    const int kwoff = Q_W;
    const int vwoff = Q_W + 2 * KV_W;

    const int tid = threadIdx.x;
    const int warp = tid >> 5;
    const int lane = tid & 31;
    const int g = lane >> 2;
    const int t4 = lane & 3;
    const int rw = warp * 16;

    const int pair = blockIdx.x;
    const int h  = blockIdx.y;
    const int b  = blockIdx.z;
    const int NQT = SEQ / 128;

    const uint32_t qa_off = (uint32_t)((rw + (lane & 15)) * QST_W + ((lane & 16) ? 4 : 0));
    const uint32_t kb_off = (uint32_t)(((lane & 7) + ((lane & 16) ? 8 : 0)) * QST_W
                                       + ((lane & 8) ? 4 : 0));

    const __half* qbase = q + (long)b * SEQ * D_MODEL + h * HD;
    const __half* kbase = k + (long)b * SEQ * D_MODEL + h * HD;
    const __half* vbase = vt + ((long)(b * NHEAD + h) * HD) * SEQ;

    auto issue_kv = [&](int buf, int kr0) {
#pragma unroll
        for (int i = 0; i < 2; i++) {
            int c = i * 256 + tid;
            int row = c >> 3, cw = c & 7;
            cpasync16(sbase + (uint32_t)(kwoff + buf * KV_W + row * QST_W + cw * 4) * 4,
                      (const char*)kbase + ((long)(kr0 + row) * 1024) * 2 + cw * 16);
            cpasync16(sbase + (uint32_t)(vwoff + buf * KV_W + row * QST_W + cw * 4) * 4,
                      (const char*)vbase + ((long)row * SEQ + kr0) * 2 + cw * 16);
        }
        CP_COMMIT();
    };

#pragma unroll 1
    for (int pass = 0; pass < 2; pass++) {
        const int qb = pass ? pair : (NQT - 1 - pair);
        const int r0 = qb * 128;
        const int wrow = r0 + rw;

        if (pass) __syncthreads();

#pragma unroll
        for (int i = 0; i < 2; i++) {
            int c = i * 256 + tid;
            int row = c >> 3, cw = c & 7;
            cpasync16(sbase + (uint32_t)(kwoff + row * QST_W + cw * 4) * 4,
                      (const char*)kbase + ((long)row * 1024) * 2 + cw * 16);
            cpasync16(sbase + (uint32_t)(vwoff + row * QST_W + cw * 4) * 4,
                      (const char*)vbase + ((long)row * SEQ) * 2 + cw * 16);
        }
#pragma unroll
        for (int i = 0; i < 4; i++) {
            int c = i * 256 + tid;
            int row = c >> 3, cw = c & 7;
            cpasync16(sbase + (uint32_t)(row * QST_W + cw * 4) * 4,
                      (const char*)qbase + ((long)(r0 + row) * 1024) * 2 + cw * 16);
        }
        CP_COMMIT();

        float m0r = -3.0e38f, m1r = -3.0e38f, l0r = 0.f, l1r = 0.f;
        float o[8][4];
#pragma unroll
        for (int ni = 0; ni < 8; ni++)
#pragma unroll
            for (int c = 0; c < 4; c++) o[ni][c] = 0.f;

        const int kb_max = 2 * qb + 1;
        for (int kb = 0; kb <= kb_max; kb++) {
            const int buf = kb & 1;
            CP_WAIT(0);
            __syncthreads();
            if (kb + 1 <= kb_max) issue_kv(buf ^ 1, (kb + 1) * 64);

            const int kr0 = kb * 64;
            const uint32_t kbb = sbase + (uint32_t)(kwoff + buf * KV_W + kb_off) * 4;
            const uint32_t vbb = sbase + (uint32_t)(vwoff + buf * KV_W + kb_off) * 4;

            if (kr0 <= wrow + 15) {
                const bool need_mask = (kr0 + 63 > wrow);

                float s[8][4];
#pragma unroll
                for (int ni = 0; ni < 8; ni++)
#pragma unroll
                    for (int c = 0; c < 4; c++) s[ni][c] = 0.f;

                // ---- S = Q K^T  (S in log2 domain via q scaling) ----
#pragma unroll
                for (int ks = 0; ks < 4; ks++) {
                    uint32_t a[4];
                    LDSM4(a[0], a[1], a[2], a[3],
                          sbase + (qa_off + (uint32_t)(ks * 8)) * 4);
                    uint32_t bf[8][2];
#pragma unroll
                    for (int nb = 0; nb < 4; nb++)
                        LDSM4(bf[2 * nb][0], bf[2 * nb][1],
                              bf[2 * nb + 1][0], bf[2 * nb + 1][1],
                              kbb + (uint32_t)(nb * 16 * QST_W + ks * 8) * 4);
#pragma unroll
                    for (int ni = 0; ni < 8; ni++)
                        mma_f16(s[ni], a, bf[ni][0], bf[ni][1]);
                }

                // ---- causal mask ----
                if (need_mask) {
                    int rg0 = wrow + g, rg1 = wrow + g + 8;
#pragma unroll
                    for (int ni = 0; ni < 8; ni++) {
                        int col = kr0 + ni * 8 + 2 * t4;
                        if (col     > rg0) s[ni][0] = -1e9f;
                        if (col + 1 > rg0) s[ni][1] = -1e9f;
                        if (col     > rg1) s[ni][2] = -1e9f;
                        if (col + 1 > rg1) s[ni][3] = -1e9f;
                    }
                }

                // ---- online softmax (base-2) ----
                float mx0 = -3.0e38f, mx1 = -3.0e38f;
#pragma unroll
                for (int ni = 0; ni < 8; ni++) {
                    mx0 = fmaxf(mx0, fmaxf(s[ni][0], s[ni][1]));
                    mx1 = fmaxf(mx1, fmaxf(s[ni][2], s[ni][3]));
                }
                mx0 = fmaxf(mx0, __shfl_xor_sync(0xffffffffu, mx0, 1));
                mx0 = fmaxf(mx0, __shfl_xor_sync(0xffffffffu, mx0, 2));
                mx1 = fmaxf(mx1, __shfl_xor_sync(0xffffffffu, mx1, 1));
                mx1 = fmaxf(mx1, __shfl_xor_sync(0xffffffffu, mx1, 2));

                float mn0 = fmaxf(m0r, mx0), mn1 = fmaxf(m1r, mx1);
                float al0 = exp2f(m0r - mn0), al1 = exp2f(m1r - mn1);
                m0r = mn0; m1r = mn1;

                float rs0 = 0.f, rs1 = 0.f;
#pragma unroll
                for (int ni = 0; ni < 8; ni++) {
                    s[ni][0] = exp2f(s[ni][0] - mn0);
                    s[ni][1] = exp2f(s[ni][1] - mn0);
                    s[ni][2] = exp2f(s[ni][2] - mn1);
                    s[ni][3] = exp2f(s[ni][3] - mn1);
                    rs0 += s[ni][0] + s[ni][1];
                    rs1 += s[ni][2] + s[ni][3];
                }
                rs0 += __shfl_xor_sync(0xffffffffu, rs0, 1);
                rs0 += __shfl_xor_sync(0xffffffffu, rs0, 2);
                rs1 += __shfl_xor_sync(0xffffffffu, rs1, 1);
                rs1 += __shfl_xor_sync(0xffffffffu, rs1, 2);
                l0r = l0r * al0 + rs0;
                l1r = l1r * al1 + rs1;

#pragma unroll
                for (int ni = 0; ni < 8; ni++) {
                    o[ni][0] *= al0; o[ni][1] *= al0;
                    o[ni][2] *= al1; o[ni][3] *= al1;
                }

                // ---- O += P V : P by register packing, V by ldmatrix ----
#pragma unroll
                for (int j = 0; j < 4; j++) {
                    uint32_t a[4];
                    a[0] = pack2(s[2 * j][0],     s[2 * j][1]);
                    a[1] = pack2(s[2 * j][2],     s[2 * j][3]);
                    a[2] = pack2(s[2 * j + 1][0], s[2 * j + 1][1]);
                    a[3] = pack2(s[2 * j + 1][2], s[2 * j + 1][3]);
                    uint32_t bf[8][2];
#pragma unroll
                    for (int nb = 0; nb < 4; nb++)
                        LDSM4(bf[2 * nb][0], bf[2 * nb][1],
                              bf[2 * nb + 1][0], bf[2 * nb + 1][1],
                              vbb + (uint32_t)(nb * 16 * QST_W + j * 8) * 4);
#pragma unroll
                    for (int ni = 0; ni < 8; ni++)
                        mma_f16(o[ni], a, bf[ni][0], bf[ni][1]);
                }
            }
        }

        // ---- normalize + write half [B,S,H,hd] ----
        float inv0 = 1.0f / l0r, inv1 = 1.0f / l1r;
        int row0 = r0 + rw + g, row1 = row0 + 8;
#pragma unroll
        for (int ni = 0; ni < 8; ni++) {
            int col = h * HD + ni * 8 + 2 * t4;
            __half2 w0 = __floats2half2_rn(o[ni][0] * inv0, o[ni][1] * inv0);
            __half2 w1 = __floats2half2_rn(o[ni][2] * inv1, o[ni][3] * inv1);
            *(__half2*)&out[((long)b * SEQ + row0) * D_MODEL + col] = w0;
            *(__half2*)&out[((long)b * SEQ + row1) * D_MODEL + col] = w1;
        }
    }
}

// ============================================================
// launch
// ============================================================
extern "C" void kernel_launch(void* const* d_in, const int* in_sizes, int n_in,
                              void* d_out, int out_size)
{
    (void)in_sizes; (void)n_in; (void)out_size;
    const float* x  = (const float*)d_in[0];
    const float* Wq = (const float*)d_in[2];
    const float* bq = (const float*)d_in[3];
    const float* Wk = (const float*)d_in[4];
    const float* Wv = (const float*)d_in[5];
    const float* bv = (const float*)d_in[6];
    const float* Wo = (const float*)d_in[7];
    const float* bo = (const float*)d_in[8];
    float* out = (float*)d_out;

    __half *qh, *kh, *vt, *ah, *xh, *wt;
    cudaGetSymbolAddress((void**)&qh, g_qh);
    cudaGetSymbolAddress((void**)&kh, g_kh);
    cudaGetSymbolAddress((void**)&vt, g_vt);
    cudaGetSymbolAddress((void**)&ah, g_ah);
    cudaGetSymbolAddress((void**)&xh, g_xh);
    cudaGetSymbolAddress((void**)&wt, g_wt);
    __half* wot = wt + (long)3 * D_MODEL * D_MODEL;

    const float scale = 0.3535533905932738f;          // 64^-0.25
    const float log2e = 1.4426950408889634f;
    const float qscale = scale * log2e;               // folds exp->exp2

    static bool attr_set = false;
    if (!attr_set) {
        cudaFuncSetAttribute(attn_h_kernel, cudaFuncAttributeMaxDynamicSharedMemorySize,
                             ATTN_SMEM_BYTES);
        cudaFuncSetAttribute(gemm_h_kernel, cudaFuncAttributeMaxDynamicSharedMemorySize,
                             GEMM_SMEM_BYTES);
        attr_set = true;
    }

    // pre-pass: fp16 conversions
    const int x4 = MROWS * D_MODEL / 4;
    x2h_kernel<<<(x4 + 255) / 256, 256>>>(x, xh, x4);
    dim3 wg(32, 32, 4);
    wtrans_kernel<<<wg, 256>>>(Wq, Wk, Wv, Wo, wt);

    // fused QKV projection: CTA tile 128x128 (proven config)
    dim3 gqkv(24, 32);
    gemm_h_kernel<<<gqkv, 256, GEMM_SMEM_BYTES>>>(
        xh, wt, bq, bv, qh, kh, vt, nullptr, qscale, scale, 0);

    // balanced paired attention
    dim3 ag(SEQ / 256, NHEAD, BATCH);
    attn_h_kernel<<<ag, 256, ATTN_SMEM_BYTES>>>(qh, kh, vt, ah);

    // output projection (fp32 out + bo)
    dim3 go(8, 32);
    gemm_h_kernel<<<go, 256, GEMM_SMEM_BYTES>>>(
        ah, wot, bo, nullptr, nullptr, nullptr, nullptr, out, 1.0f, 1.0f, 1);
}

// round 17
// speedup vs baseline: 1.0978x; 1.0108x over previous
#include <cuda_runtime.h>
#include <cuda_fp16.h>
#include <cstdint>

#define D_MODEL 1024
#define BATCH 2
#define SEQ 2048
#define NHEAD 16
#define HD 64
#define MROWS (BATCH * SEQ)   // 4096

// -------- scratch (no cudaMalloc allowed) --------
__device__ __half g_qh[MROWS * D_MODEL];
__device__ __half g_kh[MROWS * D_MODEL];
__device__ __half g_vt[BATCH * NHEAD * HD * SEQ];   // [b][h][d][s]
__device__ __half g_ah[MROWS * D_MODEL];
__device__ __half g_xh[MROWS * D_MODEL];
__device__ __half g_wt[4 * D_MODEL * D_MODEL];      // [Wq|Wk|Wv|Wo] transposed: row n, col k

// ============================================================
// helpers
// ============================================================
__device__ __forceinline__ void mma_f16(float c[4], const uint32_t a[4],
                                        uint32_t b0, uint32_t b1) {
    asm volatile(
        "mma.sync.aligned.m16n8k16.row.col.f32.f16.f16.f32 "
        "{%0,%1,%2,%3}, {%4,%5,%6,%7}, {%8,%9}, {%0,%1,%2,%3};"
        : "+f"(c[0]), "+f"(c[1]), "+f"(c[2]), "+f"(c[3])
        : "r"(a[0]), "r"(a[1]), "r"(a[2]), "r"(a[3]), "r"(b0), "r"(b1));
}
__device__ __forceinline__ uint32_t pack2(float lo, float hi) {
    __half2 h = __floats2half2_rn(lo, hi);
    return *(uint32_t*)&h;
}
__device__ __forceinline__ uint32_t smem_u32(const void* p) {
    uint32_t a;
    asm("{ .reg .u64 t; cvta.to.shared.u64 t, %1; cvt.u32.u64 %0, t; }" : "=r"(a) : "l"(p));
    return a;
}
__device__ __forceinline__ void cpasync16(uint32_t dst, const void* src) {
    asm volatile("cp.async.cg.shared.global [%0], [%1], 16;" :: "r"(dst), "l"(src));
}
#define CP_COMMIT() asm volatile("cp.async.commit_group;" ::: "memory")
#define CP_WAIT(n)  asm volatile("cp.async.wait_group %0;" :: "n"(n) : "memory")
#define LDSM4(r0, r1, r2, r3, addr) \
    asm volatile("ldmatrix.sync.aligned.m8n8.x4.shared.b16 {%0,%1,%2,%3}, [%4];" \
        : "=r"(r0), "=r"(r1), "=r"(r2), "=r"(r3) : "r"(addr))

// ============================================================
// merged pre-pass: z<4 -> weight seg transpose fp32->fp16 [n][k];
//                  z==4 -> x fp32->fp16 (strided float4 loop)
// grid: (1024, 1, 5), 256 threads
// ============================================================
__global__ __launch_bounds__(256) void prepass_kernel(
    const float* __restrict__ x,
    const float* __restrict__ w0, const float* __restrict__ w1,
    const float* __restrict__ w2, const float* __restrict__ w3,
    __half* __restrict__ xh, __half* __restrict__ wt)
{
    const int z = blockIdx.z;
    if (z == 4) {
        const int n4 = MROWS * D_MODEL / 4;   // 1M float4
        for (int i = blockIdx.x * 256 + threadIdx.x; i < n4; i += 1024 * 256) {
            float4 v = ((const float4*)x)[i];
            __half2 h0 = __floats2half2_rn(v.x, v.y);
            __half2 h1 = __floats2half2_rn(v.z, v.w);
            uint2 u;
            u.x = *(uint32_t*)&h0;
            u.y = *(uint32_t*)&h1;
            ((uint2*)xh)[i] = u;
        }
        return;
    }
    __shared__ float t[32][33];
    const float* W = (z == 0) ? w0 : (z == 1) ? w1 : (z == 2) ? w2 : w3;
    const int n0 = (blockIdx.x & 31) * 32;
    const int k0 = (blockIdx.x >> 5) * 32;
    const int tx = threadIdx.x & 31;
    const int ty = threadIdx.x >> 5;   // 0..7
#pragma unroll
    for (int i = 0; i < 4; i++)
        t[ty + 8 * i][tx] = W[(long)(k0 + ty + 8 * i) * 1024 + n0 + tx];
    __syncthreads();
#pragma unroll
    for (int i = 0; i < 4; i++) {
        int n = n0 + ty + 8 * i;
        wt[(long)(z * 1024 + n) * 1024 + k0 + tx] = __float2half_rn(t[tx][ty + 8 * i]);
    }
}

// ============================================================
// fp16 GEMM via mma.sync m16n8k16 + ldmatrix, 4-stage cp.async pipeline.
// A [m][k] half; Wt [n][k] half. CTA 128x128, BK=32, 256 threads.
// Warp grid 2(M)x4(N), warp tile 64x32. (Proven config: 2 CTAs/SM.)
// ============================================================
#define AST_W 20                 // smem row stride in words (16 data + 4 pad)
#define ABUF_W (128 * AST_W)     // 2560 words per stage buffer
#define GEMM_SMEM_BYTES (8 * ABUF_W * 4)   // 81920

__global__ __launch_bounds__(256, 2) void gemm_h_kernel(
    const __half* __restrict__ A, const __half* __restrict__ W,
    const float* __restrict__ bias0, const float* __restrict__ bias2,
    __half* __restrict__ Cq, __half* __restrict__ Ck, __half* __restrict__ Cvt,
    float* __restrict__ Cf, float qscale, float kscale, int out_mode)
{
    extern __shared__ uint32_t smw[];
    const uint32_t sbase = smem_u32(smw);

    const int tid = threadIdx.x;
    const int warp = tid >> 5;
    const int lane = tid & 31;
    const int wm = warp & 1;
    const int wn = warp >> 1;
    const int m0 = blockIdx.y * 128;
    const int n0g = blockIdx.x * 128;
    const int g = lane >> 2;
    const int t4 = lane & 3;

    const uint32_t aa_off = (uint32_t)((wm * 64 + (lane & 15)) * AST_W + ((lane & 16) ? 4 : 0));
    const uint32_t bb_off = (uint32_t)((wn * 32 + (lane & 7) + ((lane & 16) ? 8 : 0)) * AST_W
                                       + ((lane & 8) ? 4 : 0));

    float acc[4][4][4];
#pragma unroll
    for (int i = 0; i < 4; i++)
#pragma unroll
        for (int j = 0; j < 4; j++)
#pragma unroll
            for (int c = 0; c < 4; c++) acc[i][j][c] = 0.f;

    auto issue_tile = [&](int buf, int k0) {
#pragma unroll
        for (int i = 0; i < 2; i++) {
            int c = i * 256 + tid;
            int row = c >> 2, cw = c & 3;
            cpasync16(sbase + (uint32_t)(buf * ABUF_W + row * AST_W + cw * 4) * 4,
                      (const char*)A + ((long)(m0 + row) * 1024 + k0) * 2 + cw * 16);
        }
#pragma unroll
        for (int i = 0; i < 2; i++) {
            int c = i * 256 + tid;
            int row = c >> 2, cw = c & 3;
            cpasync16(sbase + (uint32_t)((4 + buf) * ABUF_W + row * AST_W + cw * 4) * 4,
                      (const char*)W + ((long)(n0g + row) * 1024 + k0) * 2 + cw * 16);
        }
        CP_COMMIT();
    };

    issue_tile(0, 0);
    issue_tile(1, 32);
    issue_tile(2, 64);

    for (int kt = 0; kt < 32; ++kt) {
        if (kt < 30)      { CP_WAIT(2); }
        else if (kt == 30){ CP_WAIT(1); }
        else              { CP_WAIT(0); }
        __syncthreads();
        if (kt + 3 < 32) issue_tile((kt + 3) & 3, (kt + 3) * 32);

        const uint32_t abase = sbase + ((kt & 3) * ABUF_W + aa_off) * 4;
        const uint32_t bbase = sbase + ((4 + (kt & 3)) * ABUF_W + bb_off) * 4;
#pragma unroll
        for (int ks = 0; ks < 2; ks++) {
            uint32_t af[4][4], bf[4][2];
#pragma unroll
            for (int mi = 0; mi < 4; mi++)
                LDSM4(af[mi][0], af[mi][1], af[mi][2], af[mi][3],
                      abase + (uint32_t)(mi * 16 * AST_W + ks * 8) * 4);
#pragma unroll
            for (int nb = 0; nb < 2; nb++)
                LDSM4(bf[2 * nb][0], bf[2 * nb][1], bf[2 * nb + 1][0], bf[2 * nb + 1][1],
                      bbase + (uint32_t)(nb * 16 * AST_W + ks * 8) * 4);
#pragma unroll
            for (int mi = 0; mi < 4; mi++)
#pragma unroll
                for (int ni = 0; ni < 4; ni++)
                    mma_f16(acc[mi][ni], af[mi], bf[ni][0], bf[ni][1]);
        }
    }

    // ---- epilogue ----
    if (out_mode == 1) {
#pragma unroll
        for (int mi = 0; mi < 4; mi++) {
            int row = m0 + wm * 64 + mi * 16 + g;
#pragma unroll
            for (int ni = 0; ni < 4; ni++) {
                int col = n0g + wn * 32 + ni * 8 + 2 * t4;
                float b0 = bias0[col], b1 = bias0[col + 1];
                float2 r0 = {acc[mi][ni][0] + b0, acc[mi][ni][1] + b1};
                float2 r1 = {acc[mi][ni][2] + b0, acc[mi][ni][3] + b1};
                *(float2*)&Cf[(long)row * 1024 + col] = r0;
                *(float2*)&Cf[(long)(row + 8) * 1024 + col] = r1;
            }
        }
    } else {
        const int seg = n0g >> 10;
        const int n0 = n0g & 1023;
#pragma unroll
        for (int mi = 0; mi < 4; mi++) {
            int row = m0 + wm * 64 + mi * 16 + g;
#pragma unroll
            for (int ni = 0; ni < 4; ni++) {
                int col = n0 + wn * 32 + ni * 8 + 2 * t4;
                if (seg == 0) {
                    float b0 = bias0[col], b1 = bias0[col + 1];
                    __half2 h0 = __floats2half2_rn((acc[mi][ni][0] + b0) * qscale,
                                                   (acc[mi][ni][1] + b1) * qscale);
                    __half2 h1 = __floats2half2_rn((acc[mi][ni][2] + b0) * qscale,
                                                   (acc[mi][ni][3] + b1) * qscale);
                    *(__half2*)&Cq[(long)row * 1024 + col] = h0;
                    *(__half2*)&Cq[(long)(row + 8) * 1024 + col] = h1;
                } else if (seg == 1) {
                    __half2 h0 = __floats2half2_rn(acc[mi][ni][0] * kscale,
                                                   acc[mi][ni][1] * kscale);
                    __half2 h1 = __floats2half2_rn(acc[mi][ni][2] * kscale,
                                                   acc[mi][ni][3] * kscale);
                    *(__half2*)&Ck[(long)row * 1024 + col] = h0;
                    *(__half2*)&Ck[(long)(row + 8) * 1024 + col] = h1;
                } else {
                    float b0 = bias2[col], b1 = bias2[col + 1];
                    int b_ = row >> 11, s_ = row & 2047;
                    int h_ = col >> 6, d_ = col & 63;
                    long base = ((long)(b_ * NHEAD + h_) * HD + d_) * SEQ;
                    Cvt[base + s_]            = __float2half_rn(acc[mi][ni][0] + b0);
                    Cvt[base + SEQ + s_]      = __float2half_rn(acc[mi][ni][1] + b1);
                    Cvt[base + s_ + 8]        = __float2half_rn(acc[mi][ni][2] + b0);
                    Cvt[base + SEQ + s_ + 8]  = __float2half_rn(acc[mi][ni][3] + b1);
                }
            }
        }
    }
}

// ============================================================
// fp16 flash attention (causal), mma m16n8k16 + ldmatrix.
// q pre-scaled by log2(e) -> softmax via exp2f.
// Paired q-tiles (p, 15-p), BM=128, BN=64, 256 threads.
// 3-stage K/V cp.async pipeline (two tiles in flight).
// ============================================================
#define QST_W 36
#define Q_W   (128 * QST_W)
#define KV_W  (64 * QST_W)
#define ATTN_SMEM_BYTES ((Q_W + 6 * KV_W) * 4)   // 73728

__global__ __launch_bounds__(256, 2) void attn_h_kernel(
    const __half* __restrict__ q, const __half* __restrict__ k,
    const __half* __restrict__ vt, __half* __restrict__ out)
{
    extern __shared__ uint32_t smw[];
    const uint32_t sbase = smem_u32(smw);
    const int kwoff = Q_W;                 // 3 K buffers
    const int vwoff = Q_W + 3 * KV_W;      // 3 V buffers

    const int tid = threadIdx.x;
    const int warp = tid >> 5;
    const int lane = tid & 31;
    const int g = lane >> 2;
    const int t4 = lane & 3;
    const int rw = warp * 16;

    const int pair = blockIdx.x;
    const int h  = blockIdx.y;
    const int b  = blockIdx.z;
    const int NQT = SEQ / 128;

    const uint32_t qa_off = (uint32_t)((rw + (lane & 15)) * QST_W + ((lane & 16) ? 4 : 0));
    const uint32_t kb_off = (uint32_t)(((lane & 7) + ((lane & 16) ? 8 : 0)) * QST_W
                                       + ((lane & 8) ? 4 : 0));

    const __half* qbase = q + (long)b * SEQ * D_MODEL + h * HD;
    const __half* kbase = k + (long)b * SEQ * D_MODEL + h * HD;
    const __half* vbase = vt + ((long)(b * NHEAD + h) * HD) * SEQ;

    auto issue_kv = [&](int buf, int kr0) {
#pragma unroll
        for (int i = 0; i < 2; i++) {
            int c = i * 256 + tid;
            int row = c >> 3, cw = c & 7;
            cpasync16(sbase + (uint32_t)(kwoff + buf * KV_W + row * QST_W + cw * 4) * 4,
                      (const char*)kbase + ((long)(kr0 + row) * 1024) * 2 + cw * 16);
            cpasync16(sbase + (uint32_t)(vwoff + buf * KV_W + row * QST_W + cw * 4) * 4,
                      (const char*)vbase + ((long)row * SEQ + kr0) * 2 + cw * 16);
        }
        CP_COMMIT();
    };

#pragma unroll 1
    for (int pass = 0; pass < 2; pass++) {
        const int qb = pass ? pair : (NQT - 1 - pair);
        const int r0 = qb * 128;
        const int wrow = r0 + rw;
        const int kb_max = 2 * qb + 1;

        if (pass) __syncthreads();   // prior pass reads done before refill

        // prologue: group0 = {K/V tile 0, Q tile}; group1 = {K/V tile 1}
#pragma unroll
        for (int i = 0; i < 2; i++) {
            int c = i * 256 + tid;
            int row = c >> 3, cw = c & 7;
            cpasync16(sbase + (uint32_t)(kwoff + row * QST_W + cw * 4) * 4,
                      (const char*)kbase + ((long)row * 1024) * 2 + cw * 16);
            cpasync16(sbase + (uint32_t)(vwoff + row * QST_W + cw * 4) * 4,
                      (const char*)vbase + ((long)row * SEQ) * 2 + cw * 16);
        }
#pragma unroll
        for (int i = 0; i < 4; i++) {
            int c = i * 256 + tid;
            int row = c >> 3, cw = c & 7;
            cpasync16(sbase + (uint32_t)(row * QST_W + cw * 4) * 4,
                      (const char*)qbase + ((long)(r0 + row) * 1024) * 2 + cw * 16);
        }
        CP_COMMIT();
        if (1 <= kb_max) issue_kv(1, 64);

        float m0r = -3.0e38f, m1r = -3.0e38f, l0r = 0.f, l1r = 0.f;
        float o[8][4];
#pragma unroll
        for (int ni = 0; ni < 8; ni++)
#pragma unroll
            for (int c = 0; c < 4; c++) o[ni][c] = 0.f;

        for (int kb = 0; kb <= kb_max; kb++) {
            const int buf = kb % 3;
            if (kb < kb_max) { CP_WAIT(1); } else { CP_WAIT(0); }
            __syncthreads();
            if (kb + 2 <= kb_max) issue_kv((kb + 2) % 3, (kb + 2) * 64);

            const int kr0 = kb * 64;
            const uint32_t kbb = sbase + (uint32_t)(kwoff + buf * KV_W + kb_off) * 4;
            const uint32_t vbb = sbase + (uint32_t)(vwoff + buf * KV_W + kb_off) * 4;

            if (kr0 <= wrow + 15) {
                const bool need_mask = (kr0 + 63 > wrow);

                float s[8][4];
#pragma unroll
                for (int ni = 0; ni < 8; ni++)
#pragma unroll
                    for (int c = 0; c < 4; c++) s[ni][c] = 0.f;

                // ---- S = Q K^T  (S in log2 domain via q scaling) ----
#pragma unroll
                for (int ks = 0; ks < 4; ks++) {
                    uint32_t a[4];
                    LDSM4(a[0], a[1], a[2], a[3],
                          sbase + (qa_off + (uint32_t)(ks * 8)) * 4);
                    uint32_t bf[8][2];
#pragma unroll
                    for (int nb = 0; nb < 4; nb++)
                        LDSM4(bf[2 * nb][0], bf[2 * nb][1],
                              bf[2 * nb + 1][0], bf[2 * nb + 1][1],
                              kbb + (uint32_t)(nb * 16 * QST_W + ks * 8) * 4);
#pragma unroll
                    for (int ni = 0; ni < 8; ni++)
                        mma_f16(s[ni], a, bf[ni][0], bf[ni][1]);
                }

                // ---- causal mask ----
                if (need_mask) {
                    int rg0 = wrow + g, rg1 = wrow + g + 8;
#pragma unroll
                    for (int ni = 0; ni < 8; ni++) {
                        int col = kr0 + ni * 8 + 2 * t4;
                        if (col     > rg0) s[ni][0] = -1e9f;
                        if (col + 1 > rg0) s[ni][1] = -1e9f;
                        if (col     > rg1) s[ni][2] = -1e9f;
                        if (col + 1 > rg1) s[ni][3] = -1e9f;
                    }
                }

                // ---- online softmax (base-2) ----
                float mx0 = -3.0e38f, mx1 = -3.0e38f;
#pragma unroll
                for (int ni = 0; ni < 8; ni++) {
                    mx0 = fmaxf(mx0, fmaxf(s[ni][0], s[ni][1]));
                    mx1 = fmaxf(mx1, fmaxf(s[ni][2], s[ni][3]));
                }
                mx0 = fmaxf(mx0, __shfl_xor_sync(0xffffffffu, mx0, 1));
                mx0 = fmaxf(mx0, __shfl_xor_sync(0xffffffffu, mx0, 2));
                mx1 = fmaxf(mx1, __shfl_xor_sync(0xffffffffu, mx1, 1));
                mx1 = fmaxf(mx1, __shfl_xor_sync(0xffffffffu, mx1, 2));

                float mn0 = fmaxf(m0r, mx0), mn1 = fmaxf(m1r, mx1);
                float al0 = exp2f(m0r - mn0), al1 = exp2f(m1r - mn1);
                m0r = mn0; m1r = mn1;

                float rs0 = 0.f, rs1 = 0.f;
#pragma unroll
                for (int ni = 0; ni < 8; ni++) {
                    s[ni][0] = exp2f(s[ni][0] - mn0);
                    s[ni][1] = exp2f(s[ni][1] - mn0);
                    s[ni][2] = exp2f(s[ni][2] - mn1);
                    s[ni][3] = exp2f(s[ni][3] - mn1);
                    rs0 += s[ni][0] + s[ni][1];
                    rs1 += s[ni][2] + s[ni][3];
                }
                rs0 += __shfl_xor_sync(0xffffffffu, rs0, 1);
                rs0 += __shfl_xor_sync(0xffffffffu, rs0, 2);
                rs1 += __shfl_xor_sync(0xffffffffu, rs1, 1);
                rs1 += __shfl_xor_sync(0xffffffffu, rs1, 2);
                l0r = l0r * al0 + rs0;
                l1r = l1r * al1 + rs1;

#pragma unroll
                for (int ni = 0; ni < 8; ni++) {
                    o[ni][0] *= al0; o[ni][1] *= al0;
                    o[ni][2] *= al1; o[ni][3] *= al1;
                }

                // ---- O += P V : P by register packing, V by ldmatrix ----
#pragma unroll
                for (int j = 0; j < 4; j++) {
                    uint32_t a[4];
                    a[0] = pack2(s[2 * j][0],     s[2 * j][1]);
                    a[1] = pack2(s[2 * j][2],     s[2 * j][3]);
                    a[2] = pack2(s[2 * j + 1][0], s[2 * j + 1][1]);
                    a[3] = pack2(s[2 * j + 1][2], s[2 * j + 1][3]);
                    uint32_t bf[8][2];
#pragma unroll
                    for (int nb = 0; nb < 4; nb++)
                        LDSM4(bf[2 * nb][0], bf[2 * nb][1],
                              bf[2 * nb + 1][0], bf[2 * nb + 1][1],
                              vbb + (uint32_t)(nb * 16 * QST_W + j * 8) * 4);
#pragma unroll
                    for (int ni = 0; ni < 8; ni++)
                        mma_f16(o[ni], a, bf[ni][0], bf[ni][1]);
                }
            }
        }

        // ---- normalize + write half [B,S,H,hd] ----
        float inv0 = 1.0f / l0r, inv1 = 1.0f / l1r;
        int row0 = r0 + rw + g, row1 = row0 + 8;
#pragma unroll
        for (int ni = 0; ni < 8; ni++) {
            int col = h * HD + ni * 8 + 2 * t4;
            __half2 w0 = __floats2half2_rn(o[ni][0] * inv0, o[ni][1] * inv0);
            __half2 w1 = __floats2half2_rn(o[ni][2] * inv1, o[ni][3] * inv1);
            *(__half2*)&out[((long)b * SEQ + row0) * D_MODEL + col] = w0;
            *(__half2*)&out[((long)b * SEQ + row1) * D_MODEL + col] = w1;
        }
    }
}

// ============================================================
// launch
// ============================================================
extern "C" void kernel_launch(void* const* d_in, const int* in_sizes, int n_in,
                              void* d_out, int out_size)
{
    (void)in_sizes; (void)n_in; (void)out_size;
    const float* x  = (const float*)d_in[0];
    const float* Wq = (const float*)d_in[2];
    const float* bq = (const float*)d_in[3];
    const float* Wk = (const float*)d_in[4];
    const float* Wv = (const float*)d_in[5];
    const float* bv = (const float*)d_in[6];
    const float* Wo = (const float*)d_in[7];
    const float* bo = (const float*)d_in[8];
    float* out = (float*)d_out;

    __half *qh, *kh, *vt, *ah, *xh, *wt;
    cudaGetSymbolAddress((void**)&qh, g_qh);
    cudaGetSymbolAddress((void**)&kh, g_kh);
    cudaGetSymbolAddress((void**)&vt, g_vt);
    cudaGetSymbolAddress((void**)&ah, g_ah);
    cudaGetSymbolAddress((void**)&xh, g_xh);
    cudaGetSymbolAddress((void**)&wt, g_wt);
    __half* wot = wt + (long)3 * D_MODEL * D_MODEL;

    const float scale = 0.3535533905932738f;          // 64^-0.25
    const float log2e = 1.4426950408889634f;
    const float qscale = scale * log2e;               // folds exp->exp2

    static bool attr_set = false;
    if (!attr_set) {
        cudaFuncSetAttribute(attn_h_kernel, cudaFuncAttributeMaxDynamicSharedMemorySize,
                             ATTN_SMEM_BYTES);
        cudaFuncSetAttribute(gemm_h_kernel, cudaFuncAttributeMaxDynamicSharedMemorySize,
                             GEMM_SMEM_BYTES);
        attr_set = true;
    }

    // merged pre-pass: weights transpose + x convert (one launch)
    dim3 pg(1024, 1, 5);
    prepass_kernel<<<pg, 256>>>(x, Wq, Wk, Wv, Wo, xh, wt);

    // fused QKV projection: CTA tile 128x128
    dim3 gqkv(24, 32);
    gemm_h_kernel<<<gqkv, 256, GEMM_SMEM_BYTES>>>(
        xh, wt, bq, bv, qh, kh, vt, nullptr, qscale, scale, 0);

    // balanced paired attention (3-stage K/V pipeline)
    dim3 ag(SEQ / 256, NHEAD, BATCH);
    attn_h_kernel<<<ag, 256, ATTN_SMEM_BYTES>>>(qh, kh, vt, ah);

    // output projection (fp32 out + bo)
    dim3 go(8, 32);
    gemm_h_kernel<<<go, 256, GEMM_SMEM_BYTES>>>(
        ah, wot, bo, nullptr, nullptr, nullptr, nullptr, out, 1.0f, 1.0f, 1);
}